// round 1
// baseline (speedup 1.0000x reference)
#include <cuda_runtime.h>
#include <cstdint>

#define N 8192
#define NW 128          // max 64-bit words per mask row (N/64)
typedef unsigned long long u64;
typedef unsigned int u32;

// ---------------- device globals (scratch; no allocation allowed) ----------------
__device__ u32 g_maxbox;
__device__ int g_cnt;
__device__ float g_x1[N], g_y1[N], g_x2[N], g_y2[N], g_sc[N];
__device__ u64 g_keys[N];
__device__ float g_sx1[N], g_sy1[N], g_sx2[N], g_sy2[N], g_ssc[N], g_sar[N];
__device__ u64 g_mask[N * NW];   // 8 MB suppression bitmask

// monotone map: float -> u32 preserving order
__device__ __forceinline__ u32 fmono(float f) {
    u32 u = __float_as_uint(f);
    return (u & 0x80000000u) ? ~u : (u | 0x80000000u);
}

__global__ void k_init() { g_maxbox = 0u; g_cnt = 0; }

// decode boxes, global max of coords, compact valid (score>0.25) sort keys, zero output
__global__ void k_prep(const float* __restrict__ p, float* __restrict__ out) {
    int i = blockIdx.x * blockDim.x + threadIdx.x;   // grid covers exactly N
    float cx = p[i], cy = p[N + i], pw = p[2*N + i], ph = p[3*N + i], s = p[4*N + i];
    float x1 = cx - pw*0.5f, y1 = cy - ph*0.5f, x2 = cx + pw*0.5f, y2 = cy + ph*0.5f;
    g_x1[i]=x1; g_y1[i]=y1; g_x2[i]=x2; g_y2[i]=y2; g_sc[i]=s;

    u32 m = fmono(fmaxf(fmaxf(x1,x2), fmaxf(y1,y2)));
    #pragma unroll
    for (int o = 16; o; o >>= 1) m = max(m, __shfl_xor_sync(0xffffffffu, m, o));
    if ((threadIdx.x & 31) == 0) atomicMax(&g_maxbox, m);

    if (s > 0.25f) {
        int slot = atomicAdd(&g_cnt, 1);
        // ascending sort => descending score, ties by ascending original index (stable)
        g_keys[slot] = ((u64)(~fmono(s)) << 32) | (u32)i;
    }
    // zero full output (rows for invalid / non-kept stay 0)
    for (int k = i; k < N*6; k += N) out[k] = 0.0f;
}

// single-block bitonic sort of up to 8192 keys (padded with max), then gather sorted boxes
__global__ __launch_bounds__(1024) void k_sort() {
    extern __shared__ u64 sk[];
    int tid = threadIdx.x;
    int cnt = g_cnt;
    for (int i = tid; i < N; i += 1024) sk[i] = (i < cnt) ? g_keys[i] : ~0ull;
    __syncthreads();
    for (int k = 2; k <= N; k <<= 1) {
        for (int j = k >> 1; j > 0; j >>= 1) {
            for (int i = tid; i < N; i += 1024) {
                int ixj = i ^ j;
                if (ixj > i) {
                    u64 a = sk[i], b = sk[ixj];
                    bool up = ((i & k) == 0);
                    if ((a > b) == up) { sk[i] = b; sk[ixj] = a; }
                }
            }
            __syncthreads();
        }
    }
    for (int kk = tid; kk < cnt; kk += 1024) {
        u64 key = sk[kk];
        int o = (int)(key & 0xFFFFFFFFull);
        float x1 = g_x1[o], y1 = g_y1[o], x2 = g_x2[o], y2 = g_y2[o];
        g_sx1[kk] = x1; g_sy1[kk] = y1; g_sx2[kk] = x2; g_sy2[kk] = y2;
        g_ssc[kk] = g_sc[o];
        g_sar[kk] = fmaxf(x2 - x1, 0.0f) * fmaxf(y2 - y1, 0.0f);
    }
}

// pairwise IoU bitmask: block computes a tile of 16 rows x 16 words (=1024 j-cols)
__global__ __launch_bounds__(256) void k_mask() {
    int cnt = g_cnt;
    int W = (cnt + 63) >> 6;
    int i0 = blockIdx.y * 16;
    int w0 = blockIdx.x * 16;
    if (i0 >= cnt || w0 >= W) return;
    if ((w0 + 16) * 64 <= i0) return;   // tile fully below diagonal: bits never read

    __shared__ float jx1[1040], jy1[1040], jx2[1040], jy2[1040], jar[1040];
    int tid = threadIdx.x;
    for (int t = tid; t < 1024; t += 256) {
        int j = w0 * 64 + t;
        int jm = (t >> 6) * 65 + (t & 63);          // +1 pad per 64 => conflict-free
        bool ok = j < cnt;
        jx1[jm] = ok ? g_sx1[j] :  3.4e38f;
        jy1[jm] = ok ? g_sy1[j] :  3.4e38f;
        jx2[jm] = ok ? g_sx2[j] : -3.4e38f;
        jy2[jm] = ok ? g_sy2[j] : -3.4e38f;
        jar[jm] = ok ? g_sar[j] : 0.0f;
    }
    __syncthreads();

    int r  = tid >> 4;          // 0..15 row within tile
    int wl = tid & 15;          // 0..15 word within tile
    int i = i0 + r;
    int w = w0 + wl;
    if (i >= cnt || w >= W) return;

    float ix1 = g_sx1[i], iy1 = g_sy1[i], ix2 = g_sx2[i], iy2 = g_sy2[i], iar = g_sar[i];
    int base = wl * 65;
    u64 bits = 0;
    #pragma unroll 8
    for (int jj = 0; jj < 64; jj++) {
        float bx1 = jx1[base + jj], by1 = jy1[base + jj];
        float bx2 = jx2[base + jj], by2 = jy2[base + jj], ba = jar[base + jj];
        float xx1 = fmaxf(ix1, bx1), yy1 = fmaxf(iy1, by1);
        float xx2 = fminf(ix2, bx2), yy2 = fminf(iy2, by2);
        float dx = fmaxf(xx2 - xx1, 0.0f), dy = fmaxf(yy2 - yy1, 0.0f);
        float inter = dx * dy;
        float uni = iar + ba - inter;
        // iou > 0.45 with "iou=0 when union<=0": div-free equivalent
        bool pred = (inter > 0.45f * uni) && (uni > 0.0f);
        bits |= ((u64)pred) << jj;
    }
    g_mask[i * NW + w] = bits;
}

// sequential greedy scan in 64-chunks + output emit (single block, 512 threads)
__global__ __launch_bounds__(512) void k_scan(float* __restrict__ out) {
    __shared__ u64 s_remv[NW];
    __shared__ u64 s_intra[64];
    __shared__ u64 s_kb;
    int tid = threadIdx.x;
    int cnt = g_cnt;
    int W = (cnt + 63) >> 6;
    float f = (g_maxbox <= 0xBF800000u) ? 1.0f : (1.0f / 416.0f);  // mono(1.0f)=0xBF800000

    for (int w = tid; w < NW; w += 512) s_remv[w] = 0ull;
    __syncthreads();

    for (int c = 0; c < W; c++) {
        if (tid < 64) {
            int i = c * 64 + tid;
            s_intra[tid] = (i < cnt) ? g_mask[i * NW + c] : 0ull;
        }
        __syncthreads();
        if (tid == 0) {
            u64 sup = s_remv[c];
            u64 kb = 0;
            int lim = min(64, cnt - c * 64);
            for (int b = 0; b < lim; b++) {
                if (!((sup >> b) & 1ull)) { kb |= 1ull << b; sup |= s_intra[b]; }
            }
            s_kb = kb;
        }
        __syncthreads();
        u64 kb = s_kb;

        // emit kept rows of this chunk
        if (tid < 64) {
            int k = c * 64 + tid;
            if (k < cnt && ((kb >> tid) & 1ull)) {
                float* o = out + k * 6;
                o[0] = g_sx1[k] * f; o[1] = g_sy1[k] * f;
                o[2] = g_sx2[k] * f; o[3] = g_sy2[k] * f;
                o[4] = g_ssc[k];     o[5] = 0.0f;
            }
        }

        // apply kept rows' masks to future words (parallel, MLP-friendly)
        int w = tid & 127;
        int g = tid >> 7;           // 0..3 row-group
        if (w > c && w < W) {
            u64 acc = 0;
            int base = c * 64;
            #pragma unroll
            for (int b2 = 0; b2 < 16; b2++) {
                int b = g * 16 + b2;
                u64 m = g_mask[(base + b) * NW + w];       // unconditional: full MLP
                acc |= (((kb >> b) & 1ull) ? m : 0ull);
            }
            if (acc) atomicOr(&s_remv[w], acc);
        }
        __syncthreads();
    }
}

extern "C" void kernel_launch(void* const* d_in, const int* in_sizes, int n_in,
                              void* d_out, int out_size) {
    const float* preds = (const float*)d_in[0];
    float* out = (float*)d_out;

    k_init<<<1, 1>>>();
    k_prep<<<N / 256, 256>>>(preds, out);

    cudaFuncSetAttribute(k_sort, cudaFuncAttributeMaxDynamicSharedMemorySize, N * sizeof(u64));
    k_sort<<<1, 1024, N * sizeof(u64)>>>();

    dim3 mg(NW / 16, N / 16);   // worst-case grid; blocks early-exit on runtime cnt
    k_mask<<<mg, 256>>>();

    k_scan<<<1, 512>>>(out);
}

// round 2
// speedup vs baseline: 2.9707x; 2.9707x over previous
#include <cuda_runtime.h>
#include <cstdint>

#define N 8192
#define NW 128          // max 64-bit words per active mask row (N/64)
typedef unsigned long long u64;
typedef unsigned int u32;

// ---------------- device globals (scratch; no allocation allowed) ----------------
__device__ u32 g_maxbox;
__device__ int g_cnt;      // valid boxes (score > 0.25)
__device__ int g_cnt_a;    // active valid boxes (positive area)
__device__ float g_x1[N], g_y1[N], g_x2[N], g_y2[N], g_sc[N];
__device__ u64 g_keys[N];  // compacted valid keys: (~mono(score))<<32 | act<<31 | idx
__device__ float g_sx1[N], g_sy1[N], g_sx2[N], g_sy2[N], g_ssc[N], g_sar[N]; // sorted actives
__device__ int g_apos[N];  // sorted-active rank -> overall sorted position
__device__ u64 g_mask[N * NW];   // suppression bitmask among actives

// monotone map: float -> u32 preserving order
__device__ __forceinline__ u32 fmono(float f) {
    u32 u = __float_as_uint(f);
    return (u & 0x80000000u) ? ~u : (u | 0x80000000u);
}

__global__ void k_init() { g_maxbox = 0u; g_cnt = 0; g_cnt_a = 0; }

// decode boxes, global max of coords, compact valid keys (+active flag), zero output
__global__ void k_prep(const float* __restrict__ p, float* __restrict__ out) {
    int i = blockIdx.x * blockDim.x + threadIdx.x;   // grid covers exactly N
    float cx = p[i], cy = p[N + i], pw = p[2*N + i], ph = p[3*N + i], s = p[4*N + i];
    float x1 = cx - pw*0.5f, y1 = cy - ph*0.5f, x2 = cx + pw*0.5f, y2 = cy + ph*0.5f;
    g_x1[i]=x1; g_y1[i]=y1; g_x2[i]=x2; g_y2[i]=y2; g_sc[i]=s;

    u32 m = fmono(fmaxf(fmaxf(x1,x2), fmaxf(y1,y2)));
    #pragma unroll
    for (int o = 16; o; o >>= 1) m = max(m, __shfl_xor_sync(0xffffffffu, m, o));
    if ((threadIdx.x & 31) == 0) atomicMax(&g_maxbox, m);

    if (s > 0.25f) {
        bool act = (x2 > x1) && (y2 > y1);     // positive area: participates in NMS
        int slot = atomicAdd(&g_cnt, 1);
        if (act) atomicAdd(&g_cnt_a, 1);
        u64 lo = ((u64)(act ? 0x80000000u : 0u)) | (u32)i;
        g_keys[slot] = ((u64)(~fmono(s)) << 32) | lo;
    }
    // zero full output (rows for invalid / non-kept stay 0)
    for (int k = i; k < N*6; k += N) out[k] = 0.0f;
}

// O(n^2) rank sort: each valid slot i gets overall rank (= output row) and
// active-rank (= position in compacted sorted-active arrays). Degenerate (passive)
// boxes are never suppressed -> emit directly. Actives scattered for mask/scan.
__global__ __launch_bounds__(256) void k_rank(float* __restrict__ out) {
    __shared__ u64 sk[1024];
    int cnt = g_cnt;
    int i = blockIdx.x * 256 + threadIdx.x;
    if (blockIdx.x * 256 >= cnt) return;

    u64 ki = (i < cnt) ? g_keys[i] : ~0ull;
    int rank_all = 0, rank_act = 0;

    for (int base = 0; base < cnt; base += 1024) {
        int lim = min(1024, cnt - base);
        __syncthreads();
        for (int t = threadIdx.x; t < lim; t += 256) sk[t] = g_keys[base + t];
        __syncthreads();
        for (int j = 0; j < lim; j++) {
            u64 kj = sk[j];
            bool lt = kj < ki;
            rank_all += lt;
            rank_act += (lt && (kj & 0x80000000ull));
        }
    }

    if (i < cnt) {
        int o = (int)(ki & 0x1FFFull);
        bool act = (ki & 0x80000000ull) != 0ull;
        float x1 = g_x1[o], y1 = g_y1[o], x2 = g_x2[o], y2 = g_y2[o], s = g_sc[o];
        if (act) {
            int r = rank_act;
            g_sx1[r]=x1; g_sy1[r]=y1; g_sx2[r]=x2; g_sy2[r]=y2;
            g_ssc[r]=s;  g_sar[r]=(x2-x1)*(y2-y1);
            g_apos[r]=rank_all;
        } else {
            // passive valid box: always kept, IoU with everything is 0
            float f = (g_maxbox <= 0xBF800000u) ? 1.0f : (1.0f / 416.0f);
            float* o6 = out + rank_all * 6;
            o6[0]=x1*f; o6[1]=y1*f; o6[2]=x2*f; o6[3]=y2*f; o6[4]=s; o6[5]=0.0f;
        }
    }
}

// pairwise IoU bitmask among actives: tile of 16 rows x 16 words (=1024 j-cols)
__global__ __launch_bounds__(256) void k_mask() {
    int cnt = g_cnt_a;
    int W = (cnt + 63) >> 6;
    int i0 = blockIdx.y * 16;
    int w0 = blockIdx.x * 16;
    if (i0 >= cnt || w0 >= W) return;
    if ((w0 + 16) * 64 <= i0) return;   // tile fully below diagonal: bits never read

    __shared__ float jx1[1040], jy1[1040], jx2[1040], jy2[1040], jar[1040];
    int tid = threadIdx.x;
    for (int t = tid; t < 1024; t += 256) {
        int j = w0 * 64 + t;
        int jm = (t >> 6) * 65 + (t & 63);          // +1 pad per 64 => conflict-free
        bool ok = j < cnt;
        jx1[jm] = ok ? g_sx1[j] :  3.4e38f;
        jy1[jm] = ok ? g_sy1[j] :  3.4e38f;
        jx2[jm] = ok ? g_sx2[j] : -3.4e38f;
        jy2[jm] = ok ? g_sy2[j] : -3.4e38f;
        jar[jm] = ok ? g_sar[j] : 0.0f;
    }
    __syncthreads();

    int r  = tid >> 4;          // 0..15 row within tile
    int wl = tid & 15;          // 0..15 word within tile
    int i = i0 + r;
    int w = w0 + wl;
    if (i >= cnt || w >= W) return;

    float ix1 = g_sx1[i], iy1 = g_sy1[i], ix2 = g_sx2[i], iy2 = g_sy2[i], iar = g_sar[i];
    int base = wl * 65;
    u64 bits = 0;
    #pragma unroll 8
    for (int jj = 0; jj < 64; jj++) {
        float bx1 = jx1[base + jj], by1 = jy1[base + jj];
        float bx2 = jx2[base + jj], by2 = jy2[base + jj], ba = jar[base + jj];
        float xx1 = fmaxf(ix1, bx1), yy1 = fmaxf(iy1, by1);
        float xx2 = fminf(ix2, bx2), yy2 = fminf(iy2, by2);
        float dx = fmaxf(xx2 - xx1, 0.0f), dy = fmaxf(yy2 - yy1, 0.0f);
        float inter = dx * dy;
        float uni = iar + ba - inter;
        bool pred = (inter > 0.45f * uni) && (uni > 0.0f);
        bits |= ((u64)pred) << jj;
    }
    g_mask[i * NW + w] = bits;
}

// sequential greedy scan over actives in 64-chunks + emit (single block, 512 threads)
__global__ __launch_bounds__(512) void k_scan(float* __restrict__ out) {
    __shared__ u64 s_remv[NW];
    __shared__ u64 s_kb;
    int tid = threadIdx.x;
    int cnt = g_cnt_a;
    int W = (cnt + 63) >> 6;
    float f = (g_maxbox <= 0xBF800000u) ? 1.0f : (1.0f / 416.0f);

    for (int w = tid; w < NW; w += 512) s_remv[w] = 0ull;
    __syncthreads();

    for (int c = 0; c < W; c++) {
        if (tid == 0) {
            u64 sup = s_remv[c];
            u64 kb = 0;
            int base = c * 64;
            #pragma unroll
            for (int g4 = 0; g4 < 4; g4++) {
                u64 m[16];
                #pragma unroll
                for (int b = 0; b < 16; b++) {
                    int row = base + g4 * 16 + b;
                    m[b] = (row < cnt) ? g_mask[(size_t)row * NW + c] : 0ull;
                }
                #pragma unroll
                for (int b = 0; b < 16; b++) {
                    int bb = g4 * 16 + b;
                    if (!((sup >> bb) & 1ull)) { kb |= 1ull << bb; sup |= m[b]; }
                }
            }
            int lim = cnt - base;
            if (lim < 64) kb &= (1ull << lim) - 1ull;
            s_kb = kb;
        }
        __syncthreads();
        u64 kb = s_kb;

        // emit kept active rows of this chunk at their overall sorted positions
        if (tid < 64) {
            int k = c * 64 + tid;
            if (k < cnt && ((kb >> tid) & 1ull)) {
                float* o = out + g_apos[k] * 6;
                o[0] = g_sx1[k] * f; o[1] = g_sy1[k] * f;
                o[2] = g_sx2[k] * f; o[3] = g_sy2[k] * f;
                o[4] = g_ssc[k];     o[5] = 0.0f;
            }
        }

        // apply kept rows' masks to future words (parallel)
        int w = tid & 127;
        int g = tid >> 7;           // 0..3 row-group
        if (w > c && w < W) {
            u64 acc = 0;
            int base = c * 64;
            #pragma unroll
            for (int b2 = 0; b2 < 16; b2++) {
                int b = g * 16 + b2;
                acc |= (((kb >> b) & 1ull) ? g_mask[(size_t)(base + b) * NW + w] : 0ull);
            }
            if (acc) atomicOr(&s_remv[w], acc);
        }
        __syncthreads();
    }
}

extern "C" void kernel_launch(void* const* d_in, const int* in_sizes, int n_in,
                              void* d_out, int out_size) {
    const float* preds = (const float*)d_in[0];
    float* out = (float*)d_out;

    k_init<<<1, 1>>>();
    k_prep<<<N / 256, 256>>>(preds, out);
    k_rank<<<N / 256, 256>>>(out);
    dim3 mg(NW / 16, N / 16);   // worst-case grid; blocks early-exit on runtime cnt
    k_mask<<<mg, 256>>>();
    k_scan<<<1, 512>>>(out);
}

// round 3
// speedup vs baseline: 3.2443x; 1.0921x over previous
#include <cuda_runtime.h>
#include <cstdint>

#define N 8192
#define NW 128          // max 64-bit words per active mask row (N/64)
typedef unsigned long long u64;
typedef unsigned int u32;

#define ACT_BIT (1ull << 13)          // active flag inside key, masked out of compares
#define KEY_CMP_MASK (~ACT_BIT)

// ---------------- device globals (zero-initialized at module load) ----------------
__device__ u32 g_maxbox;
__device__ int g_cnt;      // valid boxes (score > 0.25)
__device__ int g_cnt_a;    // active valid boxes (positive area)
__device__ float g_x1[N], g_y1[N], g_x2[N], g_y2[N], g_sc[N];
__device__ u64 g_keys[N];  // (~mono(score))<<32 | act<<13 | idx(13 bits)
__device__ float g_sx1[N], g_sy1[N], g_sx2[N], g_sy2[N], g_ssc[N], g_sar[N]; // sorted actives
__device__ int g_apos[N];  // sorted-active rank -> overall sorted position (output row)
__device__ u64 g_mask[N * NW];   // suppression bitmask among actives

__device__ __forceinline__ u32 fmono(float f) {
    u32 u = __float_as_uint(f);
    return (u & 0x80000000u) ? ~u : (u | 0x80000000u);
}

// decode boxes, global coord max, compact valid keys (+active flag), zero output
__global__ void k_prep(const float* __restrict__ p, float* __restrict__ out) {
    int i = blockIdx.x * blockDim.x + threadIdx.x;   // grid covers exactly N
    float cx = p[i], cy = p[N + i], pw = p[2*N + i], ph = p[3*N + i], s = p[4*N + i];
    float x1 = cx - pw*0.5f, y1 = cy - ph*0.5f, x2 = cx + pw*0.5f, y2 = cy + ph*0.5f;
    g_x1[i]=x1; g_y1[i]=y1; g_x2[i]=x2; g_y2[i]=y2; g_sc[i]=s;

    u32 m = fmono(fmaxf(fmaxf(x1,x2), fmaxf(y1,y2)));
    #pragma unroll
    for (int o = 16; o; o >>= 1) m = max(m, __shfl_xor_sync(0xffffffffu, m, o));
    if ((threadIdx.x & 31) == 0) atomicMax(&g_maxbox, m);

    if (s > 0.25f) {
        bool act = (x2 > x1) && (y2 > y1);     // positive area: participates in NMS
        int slot = atomicAdd(&g_cnt, 1);
        if (act) atomicAdd(&g_cnt_a, 1);
        g_keys[slot] = ((u64)(~fmono(s)) << 32) | (act ? ACT_BIT : 0ull) | (u32)i;
    }
    for (int k = i; k < N*6; k += N) out[k] = 0.0f;   // zero full output
}

// O(n^2) rank sort, j-loop split 4-ways per i. Passive boxes (zero area) are
// never suppressed and never suppress -> emitted directly here.
__global__ __launch_bounds__(1024) void k_rank(float* __restrict__ out) {
    __shared__ u64 sk[1024];
    int cnt = g_cnt;
    if (blockIdx.x * 256 >= cnt) return;
    int tid = threadIdx.x;
    int i = blockIdx.x * 256 + (tid >> 2);
    int part = tid & 3;

    u64 ki = (i < cnt) ? g_keys[i] : ~0ull;
    u64 kim = ki & KEY_CMP_MASK;
    int rank_all = 0, rank_act = 0;

    for (int base = 0; base < cnt; base += 1024) {
        int lim = min(1024, cnt - base);
        __syncthreads();
        for (int t = tid; t < lim; t += 1024) sk[t] = g_keys[base + t];
        __syncthreads();
        for (int j = part; j < lim; j += 4) {
            u64 kj = sk[j];
            bool lt = (kj & KEY_CMP_MASK) < kim;
            rank_all += lt;
            rank_act += (lt && (kj & ACT_BIT));
        }
    }
    rank_all += __shfl_xor_sync(0xffffffffu, rank_all, 1);
    rank_all += __shfl_xor_sync(0xffffffffu, rank_all, 2);
    rank_act += __shfl_xor_sync(0xffffffffu, rank_act, 1);
    rank_act += __shfl_xor_sync(0xffffffffu, rank_act, 2);

    if (part == 0 && i < cnt) {
        int o = (int)(ki & 0x1FFFull);
        bool act = (ki & ACT_BIT) != 0ull;
        float x1 = g_x1[o], y1 = g_y1[o], x2 = g_x2[o], y2 = g_y2[o], s = g_sc[o];
        if (act) {
            int r = rank_act;
            g_sx1[r]=x1; g_sy1[r]=y1; g_sx2[r]=x2; g_sy2[r]=y2;
            g_ssc[r]=s;  g_sar[r]=(x2-x1)*(y2-y1);
            g_apos[r]=rank_all;
        } else {
            float f = (g_maxbox <= 0xBF800000u) ? 1.0f : (1.0f / 416.0f);
            float* o6 = out + rank_all * 6;
            o6[0]=x1*f; o6[1]=y1*f; o6[2]=x2*f; o6[3]=y2*f; o6[4]=s; o6[5]=0.0f;
        }
    }
}

// pairwise IoU bitmask among actives: grid-stride over actual upper-triangle tiles
__global__ __launch_bounds__(256) void k_mask() {
    int cnt = g_cnt_a;
    if (cnt == 0) return;
    int W = (cnt + 63) >> 6;
    int itiles = (cnt + 15) >> 4;
    int wtiles = (W + 15) >> 4;
    int ntiles = itiles * wtiles;

    __shared__ float jx1[1040], jy1[1040], jx2[1040], jy2[1040], jar[1040];
    int tid = threadIdx.x;

    for (int t = blockIdx.x; t < ntiles; t += gridDim.x) {
        int i0 = (t / wtiles) * 16;
        int w0 = (t % wtiles) * 16;
        if ((w0 + 16) * 64 <= i0) continue;   // fully below diagonal (uniform per block)

        __syncthreads();                       // smem reuse guard
        for (int tt = tid; tt < 1024; tt += 256) {
            int j = w0 * 64 + tt;
            int jm = (tt >> 6) * 65 + (tt & 63);   // +1 pad per 64 -> conflict-free
            bool ok = j < cnt;
            jx1[jm] = ok ? g_sx1[j] :  3.4e38f;
            jy1[jm] = ok ? g_sy1[j] :  3.4e38f;
            jx2[jm] = ok ? g_sx2[j] : -3.4e38f;
            jy2[jm] = ok ? g_sy2[j] : -3.4e38f;
            jar[jm] = ok ? g_sar[j] : 0.0f;
        }
        __syncthreads();

        int r  = tid >> 4;          // row within tile
        int wl = tid & 15;          // word within tile
        int i = i0 + r;
        int w = w0 + wl;
        if (i < cnt && w < W) {
            float ix1 = g_sx1[i], iy1 = g_sy1[i], ix2 = g_sx2[i], iy2 = g_sy2[i], iar = g_sar[i];
            int base = wl * 65;
            u64 bits = 0;
            #pragma unroll 8
            for (int jj = 0; jj < 64; jj++) {
                float bx1 = jx1[base + jj], by1 = jy1[base + jj];
                float bx2 = jx2[base + jj], by2 = jy2[base + jj], ba = jar[base + jj];
                float xx1 = fmaxf(ix1, bx1), yy1 = fmaxf(iy1, by1);
                float xx2 = fminf(ix2, bx2), yy2 = fminf(iy2, by2);
                float dx = fmaxf(xx2 - xx1, 0.0f), dy = fmaxf(yy2 - yy1, 0.0f);
                float inter = dx * dy;
                float uni = iar + ba - inter;
                bool pred = (inter > 0.45f * uni) && (uni > 0.0f);
                bits |= ((u64)pred) << jj;
            }
            g_mask[(size_t)i * NW + w] = bits;
        }
    }
}

// sequential greedy scan over actives in 64-chunks, double-buffered resolve column
__global__ __launch_bounds__(512) void k_scan(float* __restrict__ out) {
    __shared__ u64 s_remv[NW];
    __shared__ u64 s_col[2][64];
    __shared__ u64 s_kb;
    int tid = threadIdx.x;
    int cnt = g_cnt_a;
    int W = (cnt + 63) >> 6;
    float f = (g_maxbox <= 0xBF800000u) ? 1.0f : (1.0f / 416.0f);

    for (int w = tid; w < NW; w += 512) s_remv[w] = 0ull;
    if (tid < 64 && W > 0) {
        s_col[0][tid] = (tid < cnt) ? g_mask[(size_t)tid * NW] : 0ull;
    }
    __syncthreads();

    for (int c = 0; c < W; c++) {
        // prefetch next chunk's resolve column (warp 2) while tid0 resolves this one
        if (tid >= 64 && tid < 128 && c + 1 < W) {
            int row = (c + 1) * 64 + (tid - 64);
            s_col[(c + 1) & 1][tid - 64] = (row < cnt) ? g_mask[(size_t)row * NW + (c + 1)] : 0ull;
        }
        if (tid == 0) {
            u64 sup = s_remv[c];
            u64 kb = 0;
            const u64* col = s_col[c & 1];
            #pragma unroll
            for (int g4 = 0; g4 < 4; g4++) {
                u64 m[16];
                #pragma unroll
                for (int b = 0; b < 16; b++) m[b] = col[g4 * 16 + b];
                #pragma unroll
                for (int b = 0; b < 16; b++) {
                    int bb = g4 * 16 + b;
                    if (!((sup >> bb) & 1ull)) { kb |= 1ull << bb; sup |= m[b]; }
                }
            }
            int lim = cnt - c * 64;
            if (lim < 64) kb &= (1ull << lim) - 1ull;
            s_kb = kb;
        }
        __syncthreads();
        u64 kb = s_kb;

        // emit kept active rows of this chunk at their overall sorted positions
        if (tid < 64) {
            int k = c * 64 + tid;
            if (k < cnt && ((kb >> tid) & 1ull)) {
                float* o = out + g_apos[k] * 6;
                o[0] = g_sx1[k] * f; o[1] = g_sy1[k] * f;
                o[2] = g_sx2[k] * f; o[3] = g_sy2[k] * f;
                o[4] = g_ssc[k];     o[5] = 0.0f;
            }
        }

        // apply kept rows' masks to future words (parallel)
        int w = tid & 127;
        int g = tid >> 7;           // 0..3 row-group
        if (w > c && w < W) {
            u64 acc = 0;
            int base = c * 64;
            #pragma unroll
            for (int b2 = 0; b2 < 16; b2++) {
                int b = g * 16 + b2;
                acc |= (((kb >> b) & 1ull) ? g_mask[(size_t)(base + b) * NW + w] : 0ull);
            }
            if (acc) atomicOr(&s_remv[w], acc);
        }
        __syncthreads();
    }

    // reset counters for the next graph replay (globals were zero at module load)
    if (tid == 0) { g_cnt = 0; g_cnt_a = 0; g_maxbox = 0u; }
}

extern "C" void kernel_launch(void* const* d_in, const int* in_sizes, int n_in,
                              void* d_out, int out_size) {
    const float* preds = (const float*)d_in[0];
    float* out = (float*)d_out;

    k_prep<<<N / 256, 256>>>(preds, out);
    k_rank<<<N / 256, 1024>>>(out);
    k_mask<<<128, 256>>>();
    k_scan<<<1, 512>>>(out);
}